// round 14
// baseline (speedup 1.0000x reference)
#include <cuda_runtime.h>
#include <cuda_fp16.h>
#include <cstdint>
#include <cstddef>

// ---------------- problem constants ----------------
#define NN     50000
#define NE     800000
#define NG     32
#define HH     128
#define NDD    16
#define EDD    128
#define DD2D   64

#define NT_E1  (NE/256)     // 3125 tiles of 256 (edge1)
#define NT_E2  (NE/128)     // 6250 tiles of 128 (edge2)
#define NT_N   (NN/16)      // 3125 node tiles of 16

// ---------------- scratch (device globals: no allocation allowed) ----------------
__device__ float g_cs[NG * HH];
// A operands pre-converted to fp16 mma-fragment form (single-rounded):
//   frag[row*32 + ks*4 + q] = {f16x2(k,k+1), f16x2(k+8,k+9)}, k = ks*16 + q*2
__device__ uint2 g_nfrag[(size_t)NN * 32];   //  12.8 MB (node features)
__device__ uint2 g_efrag[(size_t)NE * 32];   // 204.8 MB (edge attrs)

// ---------------- helpers ----------------
__device__ __forceinline__ float gelu_f(float x) {
    return 0.5f * x * (1.0f + erff(x * 0.70710678118654752440f));
}

// pack two f32 -> f16x2 (lo half = a, hi half = b)
__device__ __forceinline__ uint32_t cvt2h(float a, float b) {
    uint32_t r;
    asm("cvt.rn.f16x2.f32 %0, %1, %2;" : "=r"(r) : "f"(b), "f"(a));
    return r;
}

__device__ __forceinline__ void mma_f16(float c[4], const uint32_t a[4],
                                        uint32_t b0, uint32_t b1) {
    asm volatile("mma.sync.aligned.m16n8k16.row.col.f32.f16.f16.f32 "
                 "{%0,%1,%2,%3}, {%4,%5,%6,%7}, {%8,%9}, {%0,%1,%2,%3};"
                 : "+f"(c[0]), "+f"(c[1]), "+f"(c[2]), "+f"(c[3])
                 : "r"(a[0]), "r"(a[1]), "r"(a[2]), "r"(a[3]), "r"(b0), "r"(b1));
}

__device__ __forceinline__ void cp16(void* sdst, const void* gsrc) {
    uint32_t sa = (uint32_t)__cvta_generic_to_shared(sdst);
    asm volatile("cp.async.ca.shared.global [%0], [%1], 16;" :: "r"(sa), "l"(gsrc));
}
#define CP_COMMIT() asm volatile("cp.async.commit_group;")
#define CP_WAIT0()  asm volatile("cp.async.wait_group 0;" ::: "memory")

// 1-pass fp16 W fragment table, two nb packed per uint4:
//   sf[ks][np][lane] = {nb0.b0, nb0.b1, nb1.b0, nb1.b1},  nb0=2*np, nb1=2*np+1
template<int KDIM>
__device__ __forceinline__ void build_wtable(uint4* sf, const float* __restrict__ W,
                                             int tid, int nthreads) {
    constexpr int NKS = KDIM / 16;
    for (int idx = tid; idx < NKS * 8 * 32; idx += nthreads) {
        int li = idx & 31, np = (idx >> 5) & 7, ks = idx >> 8;
        int n0 = (2 * np) * 8 + (li >> 2);
        int n1 = n0 + 8;
        int kg = ks * 16 + (li & 3) * 2;
        uint4 f;
        f.x = cvt2h(W[(size_t)kg * HH + n0],       W[(size_t)(kg + 1) * HH + n0]);
        f.y = cvt2h(W[(size_t)(kg + 8) * HH + n0], W[(size_t)(kg + 9) * HH + n0]);
        f.z = cvt2h(W[(size_t)kg * HH + n1],       W[(size_t)(kg + 1) * HH + n1]);
        f.w = cvt2h(W[(size_t)(kg + 8) * HH + n1], W[(size_t)(kg + 9) * HH + n1]);
        sf[idx] = f;
    }
}

// ======================================================================
// Kernel 0: cs[g] = gelu(concat(emb_chg[charge], emb_spin[spin]) @ W_cs + b_cs)
// 256 threads: k-range split in two halves, smem reduce.
// ======================================================================
__global__ void cs_kernel(const int* __restrict__ charge, const int* __restrict__ spin,
                          const float* __restrict__ emb_chg, const float* __restrict__ emb_spin,
                          const float* __restrict__ W_cs, const float* __restrict__ b_cs) {
    __shared__ float xv[2 * HH];
    __shared__ float part[128];
    int g = blockIdx.x, tid = threadIdx.x;
    int j = tid & 127, h = tid >> 7;
    if (tid < HH) {
        int c = charge[g], s = spin[g];
        xv[tid]      = emb_chg[c * HH + tid];
        xv[HH + tid] = emb_spin[s * HH + tid];
    }
    __syncthreads();
    float acc = 0.f;
    const float* wp = W_cs + (size_t)h * HH * HH + j;
    const float* xp = xv + h * HH;
    #pragma unroll 8
    for (int k = 0; k < HH; k++) acc += xp[k] * wp[k * HH];
    if (h == 1) part[j] = acc;
    __syncthreads();
    if (h == 0)
        g_cs[g * HH + j] = gelu_f(acc + part[j] + b_cs[j]);
}

// ======================================================================
// Kernel 1: node features — embed/LN fp32, GEMM via fp16 HMMA 1-pass.
// Output -> g_nfrag (fp16 fragments).
// ======================================================================
#define SXS 264
#define SMEM_NODE (65536 + 16 * SXS * 4)

__global__ void __launch_bounds__(256, 1)
node_kernel(const int* __restrict__ an, const float* __restrict__ nde,
            const int* __restrict__ nbatch,
            const float* __restrict__ emb_atom, const float* __restrict__ W_nd,
            const float* __restrict__ b_nd, const float* __restrict__ ln_g,
            const float* __restrict__ ln_b, const float* __restrict__ W_node,
            const float* __restrict__ b_node) {
    extern __shared__ char dyn_smem[];
    uint4* sfW = (uint4*)dyn_smem;              // [16][8][32]
    float* sx  = (float*)(dyn_smem + 65536);    // [16][SXS]
    __shared__ float smu[16], srs[16];
    const int tid = threadIdx.x, lane = tid & 31, wid = tid >> 5;
    const int lr = lane >> 2, kc = (lane & 3) * 2;

    build_wtable<256>(sfW, W_node, tid, 256);
    __syncthreads();

    for (int t0 = blockIdx.x; t0 < NT_N; t0 += gridDim.x) {
        __syncthreads();   // sx reuse fence
        int n0 = t0 * 16;
        for (int idx = tid; idx < 16 * HH; idx += 256) {
            int n = idx >> 7, j = idx & 127;
            int node = n0 + n;
            float a = emb_atom[an[node] * HH + j];
            float accv = b_nd[j];
            const float* nrow = nde + node * NDD;
            #pragma unroll
            for (int k = 0; k < NDD; k++) accv += nrow[k] * W_nd[k * HH + j];
            sx[n * SXS + j]      = a;
            sx[n * SXS + HH + j] = gelu_f(accv);
        }
        __syncthreads();
        for (int n = wid; n < 16; n += 8) {
            float s1 = 0.f, s2 = 0.f;
            for (int k = lane; k < 256; k += 32) {
                float v = sx[n * SXS + k]; s1 += v; s2 += v * v;
            }
            #pragma unroll
            for (int o = 16; o > 0; o >>= 1) {
                s1 += __shfl_down_sync(0xffffffffu, s1, o);
                s2 += __shfl_down_sync(0xffffffffu, s2, o);
            }
            if (lane == 0) {
                float mu  = s1 * (1.f / 256.f);
                float var = s2 * (1.f / 256.f) - mu * mu;
                smu[n] = mu; srs[n] = rsqrtf(var + 1e-5f);
            }
        }
        __syncthreads();
        for (int idx = tid; idx < 16 * 256; idx += 256) {
            int n = idx >> 8, k = idx & 255;
            sx[n * SXS + k] =
                (sx[n * SXS + k] - smu[n]) * srs[n] * ln_g[k] + ln_b[k];
        }
        __syncthreads();
        // ---- GEMM [16,256]@[256,128]; warp handles nb = 2*wid, 2*wid+1
        {
            float acc[2][4];
            #pragma unroll
            for (int i = 0; i < 2; i++) {
                float2 b = *(const float2*)(b_node + (wid * 2 + i) * 8 + kc);
                acc[i][0] = b.x; acc[i][1] = b.y; acc[i][2] = b.x; acc[i][3] = b.y;
            }
            #pragma unroll
            for (int ks = 0; ks < 16; ks++) {
                const float* x0 = sx + lr * SXS + ks * 16 + kc;
                const float* x1 = x0 + 8 * SXS;
                uint32_t ah[4];
                ah[0] = cvt2h(x0[0], x0[1]);
                ah[1] = cvt2h(x1[0], x1[1]);
                ah[2] = cvt2h(x0[8], x0[9]);
                ah[3] = cvt2h(x1[8], x1[9]);
                uint4 f = sfW[ks * 256 + wid * 32 + lane];
                mma_f16(acc[0], ah, f.x, f.y);
                mma_f16(acc[1], ah, f.z, f.w);
            }
            // epilogue: gelu + cs add, convert to fp16 fragment form.
            const int node0 = n0 + lr, node1 = node0 + 8;
            const float* cs0 = g_cs + nbatch[node0] * HH;
            const float* cs1 = g_cs + nbatch[node1] * HH;
            const int col0 = wid * 16 + kc;
            const int col1 = col0 + 8;
            uint32_t h0, h1;
            h0 = cvt2h(gelu_f(acc[0][0]) + cs0[col0], gelu_f(acc[0][1]) + cs0[col0 + 1]);
            h1 = cvt2h(gelu_f(acc[1][0]) + cs0[col1], gelu_f(acc[1][1]) + cs0[col1 + 1]);
            g_nfrag[(size_t)node0 * 32 + wid * 4 + (kc >> 1)] = make_uint2(h0, h1);
            h0 = cvt2h(gelu_f(acc[0][2]) + cs1[col0], gelu_f(acc[0][3]) + cs1[col0 + 1]);
            h1 = cvt2h(gelu_f(acc[1][2]) + cs1[col1], gelu_f(acc[1][3]) + cs1[col1 + 1]);
            g_nfrag[(size_t)node1 * 32 + wid * 4 + (kc >> 1)] = make_uint2(h0, h1);
        }
    }
}

// ======================================================================
// Edge kernel 1: eattr = gelu([edist|edir] @ W_edge + b_edge), K=192.
// 512 threads, 16 warps 8(m)x2(n), warp tile 32x64, tile = 256 edges.
// fp16 1-pass; A prefetch depth 2. Output -> g_efrag (fp16 fragments).
// ======================================================================
__global__ void __launch_bounds__(512, 1)
edge1_hmma(const float* __restrict__ P0, const float* __restrict__ P1,
           const float* __restrict__ W, const float* __restrict__ bias)
{
    constexpr int NKS = 12;
    extern __shared__ char dyn_smem[];
    uint4* sf = (uint4*)dyn_smem;          // [12][8][32]

    const int tid = threadIdx.x, lane = tid & 31, wid = tid >> 5;
    const int warp_m = wid & 7, warp_n = wid >> 3;
    const int lr = lane >> 2, kc = (lane & 3) * 2, q = lane & 3;

    build_wtable<192>(sf, W, tid, 512);
    __syncthreads();

    const uint4* wfl = sf + (size_t)warp_n * 4 * 32 + lane;

    for (int tile = blockIdx.x; tile < NT_E1; tile += gridDim.x) {
        const int e0 = tile * 256;
        const int mb0 = e0 + warp_m * 32 + lr;   // rows: mb0 + r*8, r=0..3
        const float* pA = P0 + (size_t)mb0 * EDD + kc;
        const float* pB = P1 + (size_t)mb0 * DD2D + kc;

        float acc[2][8][4];
        #pragma unroll
        for (int i = 0; i < 8; i++) {
            float2 b = *(const float2*)(bias + (warp_n * 8 + i) * 8 + kc);
            #pragma unroll
            for (int mf = 0; mf < 2; mf++) {
                acc[mf][i][0] = b.x; acc[mf][i][1] = b.y;
                acc[mf][i][2] = b.x; acc[mf][i][3] = b.y;
            }
        }

        float2 v0[4][2], v1[4][2];
        #define LOADA(KG, VV)                                                      \
        {                                                                          \
            _Pragma("unroll")                                                      \
            for (int r = 0; r < 4; r++) {                                          \
                const float* qq = ((KG) < 128) ? pA + r * 8 * EDD + (KG)           \
                                               : pB + r * 8 * DD2D + ((KG) - 128); \
                (VV)[r][0] = *(const float2*)qq;                                   \
                (VV)[r][1] = *(const float2*)(qq + 8);                             \
            }                                                                      \
        }

        LOADA(0, v0);
        LOADA(16, v1);

        #pragma unroll
        for (int ks = 0; ks < NKS; ks++) {
            float2 (*cur)[2] = (ks & 1) ? v1 : v0;
            uint32_t ah0[4], ah1[4];
            ah0[0] = cvt2h(cur[0][0].x, cur[0][0].y);
            ah0[1] = cvt2h(cur[1][0].x, cur[1][0].y);
            ah0[2] = cvt2h(cur[0][1].x, cur[0][1].y);
            ah0[3] = cvt2h(cur[1][1].x, cur[1][1].y);
            ah1[0] = cvt2h(cur[2][0].x, cur[2][0].y);
            ah1[1] = cvt2h(cur[3][0].x, cur[3][0].y);
            ah1[2] = cvt2h(cur[2][1].x, cur[2][1].y);
            ah1[3] = cvt2h(cur[3][1].x, cur[3][1].y);
            if (ks + 2 < NKS) {
                if (ks & 1) { LOADA((ks + 2) * 16, v1); }
                else        { LOADA((ks + 2) * 16, v0); }
            }

            const uint4* wk = wfl + ks * 256;
            #pragma unroll
            for (int j = 0; j < 4; j++) {
                uint4 f = wk[j * 32];
                mma_f16(acc[0][2 * j + 0], ah0, f.x, f.y);
                mma_f16(acc[0][2 * j + 1], ah0, f.z, f.w);
                mma_f16(acc[1][2 * j + 0], ah1, f.x, f.y);
                mma_f16(acc[1][2 * j + 1], ah1, f.z, f.w);
            }
        }
        #undef LOADA

        // ---- epilogue: gelu, convert to fp16 fragments.
        #pragma unroll
        for (int mf = 0; mf < 2; mf++) {
            const size_t ra = (size_t)(mb0 + mf * 16);
            #pragma unroll
            for (int j = 0; j < 4; j++) {
                const int i0 = 2 * j, i1 = 2 * j + 1;
                const int ksIdx = warp_n * 4 + j;
                uint32_t h0, h1;
                h0 = cvt2h(gelu_f(acc[mf][i0][0]), gelu_f(acc[mf][i0][1]));
                h1 = cvt2h(gelu_f(acc[mf][i1][0]), gelu_f(acc[mf][i1][1]));
                g_efrag[ra * 32 + ksIdx * 4 + q] = make_uint2(h0, h1);
                h0 = cvt2h(gelu_f(acc[mf][i0][2]), gelu_f(acc[mf][i0][3]));
                h1 = cvt2h(gelu_f(acc[mf][i1][2]), gelu_f(acc[mf][i1][3]));
                g_efrag[(ra + 8) * 32 + ksIdx * 4 + q] = make_uint2(h0, h1);
            }
        }
    }
}

// ======================================================================
// Edge kernel 2: out = gelu([node[src]|eattr] @ W_ef + b_ef), K=256.
// cp.async TILE PIPELINE: full A panel (node gather 256B/row + eattr
// 256B/row) staged gmem->smem one tile ahead, double buffered.
// Tile = 128 edges; 512 threads, 16 warps 8(m)x2(n), warp tile 16x64.
// Mainloop is pure LDS+MMA: 2x LDS.64 (A) + 4x LDS.128 (W) + 8 MMA /kstep.
// smem: W table 64K + 2 x 128 x 528B A panels = 200,704 B.
// ======================================================================
#define AROW 528
#define SMEM_E2 (65536 + 2 * 128 * AROW)

__global__ void __launch_bounds__(512, 1)
edge2_hmma(const int* __restrict__ srcIdx, const float* __restrict__ W,
           const float* __restrict__ bias, float* __restrict__ outp)
{
    extern __shared__ char dyn_smem[];
    uint4* sf = (uint4*)dyn_smem;          // [16][8][32] = 65536 B
    char*  sA = dyn_smem + 65536;          // [2][128][AROW]

    const int tid = threadIdx.x, lane = tid & 31, wid = tid >> 5;
    const int warp_m = wid & 7, warp_n = wid >> 3;
    const int lr = lane >> 2, kc = (lane & 3) * 2, q = lane & 3;

    build_wtable<256>(sf, W, tid, 512);

    const uint4* wfl = sf + (size_t)warp_n * 4 * 32 + lane;

    // cp.async staging role: thread -> (row, 128B quarter of the 512B row)
    const int srow  = tid >> 2;          // 0..127
    const int spart = tid & 3;           // 0,1: node halves; 2,3: eattr halves

    #define STAGE(T, B)                                                            \
    {                                                                              \
        const int e = (T) * 128 + srow;                                            \
        const char* src;                                                           \
        if (spart < 2)                                                             \
            src = (const char*)g_nfrag + (size_t)srcIdx[e] * 256 + spart * 128;    \
        else                                                                       \
            src = (const char*)g_efrag + (size_t)e * 256 + (spart - 2) * 128;      \
        char* dst = sA + (B) * (128 * AROW) + srow * AROW + spart * 128;           \
        _Pragma("unroll")                                                          \
        for (int i = 0; i < 8; i++) cp16(dst + i * 16, src + i * 16);              \
        CP_COMMIT();                                                               \
    }

    int buf = 0;
    if (blockIdx.x < NT_E2) STAGE(blockIdx.x, 0);

    for (int tile = blockIdx.x; tile < NT_E2; tile += gridDim.x) {
        CP_WAIT0();
        __syncthreads();                 // A panel [buf] ready; [buf^1] free

        const int nxt = tile + gridDim.x;
        if (nxt < NT_E2) STAGE(nxt, buf ^ 1);

        // ---- mainloop: warp tile 16 rows x 64 cols ----
        float acc[8][4];
        #pragma unroll
        for (int i = 0; i < 8; i++) {
            float2 b = *(const float2*)(bias + (warp_n * 8 + i) * 8 + kc);
            acc[i][0] = b.x; acc[i][1] = b.y; acc[i][2] = b.x; acc[i][3] = b.y;
        }

        const char* ab = sA + buf * (128 * AROW) + (warp_m * 16 + lr) * AROW + q * 8;
        #pragma unroll
        for (int ks = 0; ks < 16; ks++) {
            uint2 a0 = *(const uint2*)(ab + ks * 32);
            uint2 a1 = *(const uint2*)(ab + 8 * AROW + ks * 32);
            uint32_t ah[4] = {a0.x, a1.x, a0.y, a1.y};
            const uint4* wk = wfl + ks * 256;
            #pragma unroll
            for (int j = 0; j < 4; j++) {
                uint4 f = wk[j * 32];
                mma_f16(acc[2 * j + 0], ah, f.x, f.y);
                mma_f16(acc[2 * j + 1], ah, f.z, f.w);
            }
        }

        // ---- epilogue: gelu + fp32 store ----
        const int mb0 = tile * 128 + warp_m * 16 + lr;
        #pragma unroll
        for (int i = 0; i < 8; i++) {
            const int col = (warp_n * 8 + i) * 8 + kc;
            float2 o0, o1;
            o0.x = gelu_f(acc[i][0]); o0.y = gelu_f(acc[i][1]);
            o1.x = gelu_f(acc[i][2]); o1.y = gelu_f(acc[i][3]);
            *(float2*)(outp + (size_t)mb0 * HH + col)       = o0;
            *(float2*)(outp + (size_t)(mb0 + 8) * HH + col) = o1;
        }

        buf ^= 1;
    }
    #undef STAGE
}

#define SMEM_E1 (12 * 8 * 32 * 16)   // 49,152 B

// ======================================================================
// launch
// ======================================================================
extern "C" void kernel_launch(void* const* d_in, const int* in_sizes, int n_in,
                              void* d_out, int out_size) {
    const int*   atomic_numbers = (const int*)  d_in[0];
    const float* nde            = (const float*)d_in[1];
    const float* edist          = (const float*)d_in[2];
    const float* edir           = (const float*)d_in[3];
    const int*   charge         = (const int*)  d_in[4];
    const int*   spin           = (const int*)  d_in[5];
    const int*   nbatch         = (const int*)  d_in[6];
    const int*   nsrc           = (const int*)  d_in[7];
    const float* emb_atom       = (const float*)d_in[8];
    const float* W_nd           = (const float*)d_in[9];
    const float* b_nd           = (const float*)d_in[10];
    const float* ln_g           = (const float*)d_in[11];
    const float* ln_b           = (const float*)d_in[12];
    const float* W_node         = (const float*)d_in[13];
    const float* b_node         = (const float*)d_in[14];
    const float* emb_chg        = (const float*)d_in[15];
    const float* emb_spin       = (const float*)d_in[16];
    const float* W_cs           = (const float*)d_in[17];
    const float* b_cs           = (const float*)d_in[18];
    const float* W_edge         = (const float*)d_in[19];
    const float* b_edge         = (const float*)d_in[20];
    const float* W_ef           = (const float*)d_in[21];
    const float* b_ef           = (const float*)d_in[22];
    float* out = (float*)d_out;

    cudaFuncSetAttribute(node_kernel, cudaFuncAttributeMaxDynamicSharedMemorySize, SMEM_NODE);
    cudaFuncSetAttribute(edge1_hmma,  cudaFuncAttributeMaxDynamicSharedMemorySize, SMEM_E1);
    cudaFuncSetAttribute(edge2_hmma,  cudaFuncAttributeMaxDynamicSharedMemorySize, SMEM_E2);

    int nsm = 148;
    cudaDeviceGetAttribute(&nsm, cudaDevAttrMultiProcessorCount, 0);

    cs_kernel<<<NG, 256>>>(charge, spin, emb_chg, emb_spin, W_cs, b_cs);
    node_kernel<<<nsm, 256, SMEM_NODE>>>(atomic_numbers, nde, nbatch, emb_atom,
                                         W_nd, b_nd, ln_g, ln_b, W_node, b_node);
    edge1_hmma<<<nsm, 512, SMEM_E1>>>(edist, edir, W_edge, b_edge);
    edge2_hmma<<<nsm, 512, SMEM_E2>>>(nsrc, W_ef, b_ef, out);
}

// round 15
// speedup vs baseline: 1.0787x; 1.0787x over previous
#include <cuda_runtime.h>
#include <cuda_fp16.h>
#include <cstdint>
#include <cstddef>

// ---------------- problem constants ----------------
#define NN     50000
#define NE     800000
#define NG     32
#define HH     128
#define NDD    16
#define EDD    128
#define DD2D   64

#define NT_E   (NE/128)     // 6250 edge tiles of 128 (both edge kernels)
#define NT_N   (NN/16)      // 3125 node tiles of 16

// ---------------- scratch (device globals: no allocation allowed) ----------------
__device__ float g_cs[NG * HH];
// A operands pre-converted to fp16 mma-fragment form (single-rounded):
//   frag[row*32 + ks*4 + q] = {f16x2(k,k+1), f16x2(k+8,k+9)}, k = ks*16 + q*2
__device__ uint2 g_nfrag[(size_t)NN * 32];   //  12.8 MB (node features)
__device__ uint2 g_efrag[(size_t)NE * 32];   // 204.8 MB (edge attrs)

// ---------------- helpers ----------------
__device__ __forceinline__ float gelu_f(float x) {
    return 0.5f * x * (1.0f + erff(x * 0.70710678118654752440f));
}

// pack two f32 -> f16x2 (lo half = a, hi half = b)
__device__ __forceinline__ uint32_t cvt2h(float a, float b) {
    uint32_t r;
    asm("cvt.rn.f16x2.f32 %0, %1, %2;" : "=r"(r) : "f"(b), "f"(a));
    return r;
}

__device__ __forceinline__ void mma_f16(float c[4], const uint32_t a[4],
                                        uint32_t b0, uint32_t b1) {
    asm volatile("mma.sync.aligned.m16n8k16.row.col.f32.f16.f16.f32 "
                 "{%0,%1,%2,%3}, {%4,%5,%6,%7}, {%8,%9}, {%0,%1,%2,%3};"
                 : "+f"(c[0]), "+f"(c[1]), "+f"(c[2]), "+f"(c[3])
                 : "r"(a[0]), "r"(a[1]), "r"(a[2]), "r"(a[3]), "r"(b0), "r"(b1));
}

// 1-pass fp16 W fragment table, two nb packed per uint4:
//   sf[ks][np][lane] = {nb0.b0, nb0.b1, nb1.b0, nb1.b1},  nb0=2*np, nb1=2*np+1
template<int KDIM>
__device__ __forceinline__ void build_wtable(uint4* sf, const float* __restrict__ W,
                                             int tid, int nthreads) {
    constexpr int NKS = KDIM / 16;
    for (int idx = tid; idx < NKS * 8 * 32; idx += nthreads) {
        int li = idx & 31, np = (idx >> 5) & 7, ks = idx >> 8;
        int n0 = (2 * np) * 8 + (li >> 2);
        int n1 = n0 + 8;
        int kg = ks * 16 + (li & 3) * 2;
        uint4 f;
        f.x = cvt2h(W[(size_t)kg * HH + n0],       W[(size_t)(kg + 1) * HH + n0]);
        f.y = cvt2h(W[(size_t)(kg + 8) * HH + n0], W[(size_t)(kg + 9) * HH + n0]);
        f.z = cvt2h(W[(size_t)kg * HH + n1],       W[(size_t)(kg + 1) * HH + n1]);
        f.w = cvt2h(W[(size_t)(kg + 8) * HH + n1], W[(size_t)(kg + 9) * HH + n1]);
        sf[idx] = f;
    }
}

// ======================================================================
// Kernel 0: cs[g] = gelu(concat(emb_chg[charge], emb_spin[spin]) @ W_cs + b_cs)
// 256 threads: k-range split in two halves, smem reduce.
// ======================================================================
__global__ void cs_kernel(const int* __restrict__ charge, const int* __restrict__ spin,
                          const float* __restrict__ emb_chg, const float* __restrict__ emb_spin,
                          const float* __restrict__ W_cs, const float* __restrict__ b_cs) {
    __shared__ float xv[2 * HH];
    __shared__ float part[128];
    int g = blockIdx.x, tid = threadIdx.x;
    int j = tid & 127, h = tid >> 7;
    if (tid < HH) {
        int c = charge[g], s = spin[g];
        xv[tid]      = emb_chg[c * HH + tid];
        xv[HH + tid] = emb_spin[s * HH + tid];
    }
    __syncthreads();
    float acc = 0.f;
    const float* wp = W_cs + (size_t)h * HH * HH + j;
    const float* xp = xv + h * HH;
    #pragma unroll 8
    for (int k = 0; k < HH; k++) acc += xp[k] * wp[k * HH];
    if (h == 1) part[j] = acc;
    __syncthreads();
    if (h == 0)
        g_cs[g * HH + j] = gelu_f(acc + part[j] + b_cs[j]);
}

// ======================================================================
// Kernel 1: node features — embed/LN fp32, GEMM via fp16 HMMA 1-pass.
// Output -> g_nfrag (fp16 fragments).
// ======================================================================
#define SXS 264
#define SMEM_NODE (65536 + 16 * SXS * 4)

__global__ void __launch_bounds__(256, 1)
node_kernel(const int* __restrict__ an, const float* __restrict__ nde,
            const int* __restrict__ nbatch,
            const float* __restrict__ emb_atom, const float* __restrict__ W_nd,
            const float* __restrict__ b_nd, const float* __restrict__ ln_g,
            const float* __restrict__ ln_b, const float* __restrict__ W_node,
            const float* __restrict__ b_node) {
    extern __shared__ char dyn_smem[];
    uint4* sfW = (uint4*)dyn_smem;              // [16][8][32]
    float* sx  = (float*)(dyn_smem + 65536);    // [16][SXS]
    __shared__ float smu[16], srs[16];
    const int tid = threadIdx.x, lane = tid & 31, wid = tid >> 5;
    const int lr = lane >> 2, kc = (lane & 3) * 2;

    build_wtable<256>(sfW, W_node, tid, 256);
    __syncthreads();

    for (int t0 = blockIdx.x; t0 < NT_N; t0 += gridDim.x) {
        __syncthreads();   // sx reuse fence
        int n0 = t0 * 16;
        for (int idx = tid; idx < 16 * HH; idx += 256) {
            int n = idx >> 7, j = idx & 127;
            int node = n0 + n;
            float a = emb_atom[an[node] * HH + j];
            float accv = b_nd[j];
            const float* nrow = nde + node * NDD;
            #pragma unroll
            for (int k = 0; k < NDD; k++) accv += nrow[k] * W_nd[k * HH + j];
            sx[n * SXS + j]      = a;
            sx[n * SXS + HH + j] = gelu_f(accv);
        }
        __syncthreads();
        for (int n = wid; n < 16; n += 8) {
            float s1 = 0.f, s2 = 0.f;
            for (int k = lane; k < 256; k += 32) {
                float v = sx[n * SXS + k]; s1 += v; s2 += v * v;
            }
            #pragma unroll
            for (int o = 16; o > 0; o >>= 1) {
                s1 += __shfl_down_sync(0xffffffffu, s1, o);
                s2 += __shfl_down_sync(0xffffffffu, s2, o);
            }
            if (lane == 0) {
                float mu  = s1 * (1.f / 256.f);
                float var = s2 * (1.f / 256.f) - mu * mu;
                smu[n] = mu; srs[n] = rsqrtf(var + 1e-5f);
            }
        }
        __syncthreads();
        for (int idx = tid; idx < 16 * 256; idx += 256) {
            int n = idx >> 8, k = idx & 255;
            sx[n * SXS + k] =
                (sx[n * SXS + k] - smu[n]) * srs[n] * ln_g[k] + ln_b[k];
        }
        __syncthreads();
        // ---- GEMM [16,256]@[256,128]; warp handles nb = 2*wid, 2*wid+1
        {
            float acc[2][4];
            #pragma unroll
            for (int i = 0; i < 2; i++) {
                float2 b = *(const float2*)(b_node + (wid * 2 + i) * 8 + kc);
                acc[i][0] = b.x; acc[i][1] = b.y; acc[i][2] = b.x; acc[i][3] = b.y;
            }
            #pragma unroll
            for (int ks = 0; ks < 16; ks++) {
                const float* x0 = sx + lr * SXS + ks * 16 + kc;
                const float* x1 = x0 + 8 * SXS;
                uint32_t ah[4];
                ah[0] = cvt2h(x0[0], x0[1]);
                ah[1] = cvt2h(x1[0], x1[1]);
                ah[2] = cvt2h(x0[8], x0[9]);
                ah[3] = cvt2h(x1[8], x1[9]);
                uint4 f = sfW[ks * 256 + wid * 32 + lane];
                mma_f16(acc[0], ah, f.x, f.y);
                mma_f16(acc[1], ah, f.z, f.w);
            }
            // epilogue: gelu + cs add, convert to fp16 fragment form.
            const int node0 = n0 + lr, node1 = node0 + 8;
            const float* cs0 = g_cs + nbatch[node0] * HH;
            const float* cs1 = g_cs + nbatch[node1] * HH;
            const int col0 = wid * 16 + kc;
            const int col1 = col0 + 8;
            uint32_t h0, h1;
            h0 = cvt2h(gelu_f(acc[0][0]) + cs0[col0], gelu_f(acc[0][1]) + cs0[col0 + 1]);
            h1 = cvt2h(gelu_f(acc[1][0]) + cs0[col1], gelu_f(acc[1][1]) + cs0[col1 + 1]);
            g_nfrag[(size_t)node0 * 32 + wid * 4 + (kc >> 1)] = make_uint2(h0, h1);
            h0 = cvt2h(gelu_f(acc[0][2]) + cs1[col0], gelu_f(acc[0][3]) + cs1[col0 + 1]);
            h1 = cvt2h(gelu_f(acc[1][2]) + cs1[col1], gelu_f(acc[1][3]) + cs1[col1 + 1]);
            g_nfrag[(size_t)node1 * 32 + wid * 4 + (kc >> 1)] = make_uint2(h0, h1);
        }
    }
}

// ======================================================================
// Edge kernel 1: eattr = gelu([edist|edir] @ W_edge + b_edge), K=192.
// 256 threads, 8 warps 4(m)x2(n), warp tile 32x64, tile = 128 edges.
// Ring-4 A prefetch (distance 3 ksteps ~ DRAM latency).
// Output -> g_efrag (fp16 fragments).
// ======================================================================
__global__ void __launch_bounds__(256, 1)
edge1_hmma(const float* __restrict__ P0, const float* __restrict__ P1,
           const float* __restrict__ W, const float* __restrict__ bias)
{
    constexpr int NKS = 12;
    extern __shared__ char dyn_smem[];
    uint4* sf = (uint4*)dyn_smem;          // [12][8][32]

    const int tid = threadIdx.x, lane = tid & 31, wid = tid >> 5;
    const int warp_m = wid & 3, warp_n = wid >> 2;
    const int lr = lane >> 2, kc = (lane & 3) * 2, q = lane & 3;

    build_wtable<192>(sf, W, tid, 256);
    __syncthreads();

    const uint4* wfl = sf + (size_t)warp_n * 4 * 32 + lane;

    for (int tile = blockIdx.x; tile < NT_E; tile += gridDim.x) {
        const int mb0 = tile * 128 + warp_m * 32 + lr;   // rows: mb0 + r*8
        const float* pA = P0 + (size_t)mb0 * EDD + kc;
        const float* pB = P1 + (size_t)mb0 * DD2D + kc;

        float acc[2][8][4];
        #pragma unroll
        for (int i = 0; i < 8; i++) {
            float2 b = *(const float2*)(bias + (warp_n * 8 + i) * 8 + kc);
            #pragma unroll
            for (int mf = 0; mf < 2; mf++) {
                acc[mf][i][0] = b.x; acc[mf][i][1] = b.y;
                acc[mf][i][2] = b.x; acc[mf][i][3] = b.y;
            }
        }

        float2 vr[4][4][2];   // ring-4 x 4 rows x 2 k-halves
        #define LOADA(KG, VV)                                                      \
        {                                                                          \
            _Pragma("unroll")                                                      \
            for (int r = 0; r < 4; r++) {                                          \
                const float* qq = ((KG) < 128) ? pA + r * 8 * EDD + (KG)           \
                                               : pB + r * 8 * DD2D + ((KG) - 128); \
                (VV)[r][0] = *(const float2*)qq;                                   \
                (VV)[r][1] = *(const float2*)(qq + 8);                             \
            }                                                                      \
        }

        LOADA(0,  vr[0]);
        LOADA(16, vr[1]);
        LOADA(32, vr[2]);

        #pragma unroll
        for (int ks = 0; ks < NKS; ks++) {
            float2 (*cur)[2] = vr[ks & 3];
            if (ks + 3 < NKS) LOADA((ks + 3) * 16, vr[(ks + 3) & 3]);
            uint32_t ah0[4], ah1[4];
            ah0[0] = cvt2h(cur[0][0].x, cur[0][0].y);
            ah0[1] = cvt2h(cur[1][0].x, cur[1][0].y);
            ah0[2] = cvt2h(cur[0][1].x, cur[0][1].y);
            ah0[3] = cvt2h(cur[1][1].x, cur[1][1].y);
            ah1[0] = cvt2h(cur[2][0].x, cur[2][0].y);
            ah1[1] = cvt2h(cur[3][0].x, cur[3][0].y);
            ah1[2] = cvt2h(cur[2][1].x, cur[2][1].y);
            ah1[3] = cvt2h(cur[3][1].x, cur[3][1].y);

            const uint4* wk = wfl + ks * 256;
            #pragma unroll
            for (int j = 0; j < 4; j++) {
                uint4 f = wk[j * 32];
                mma_f16(acc[0][2 * j + 0], ah0, f.x, f.y);
                mma_f16(acc[0][2 * j + 1], ah0, f.z, f.w);
                mma_f16(acc[1][2 * j + 0], ah1, f.x, f.y);
                mma_f16(acc[1][2 * j + 1], ah1, f.z, f.w);
            }
        }
        #undef LOADA

        // ---- epilogue: gelu, convert to fp16 fragments.
        #pragma unroll
        for (int mf = 0; mf < 2; mf++) {
            const size_t ra = (size_t)(mb0 + mf * 16);
            #pragma unroll
            for (int j = 0; j < 4; j++) {
                const int i0 = 2 * j, i1 = 2 * j + 1;
                const int ksIdx = warp_n * 4 + j;
                uint32_t h0, h1;
                h0 = cvt2h(gelu_f(acc[mf][i0][0]), gelu_f(acc[mf][i0][1]));
                h1 = cvt2h(gelu_f(acc[mf][i1][0]), gelu_f(acc[mf][i1][1]));
                g_efrag[ra * 32 + ksIdx * 4 + q] = make_uint2(h0, h1);
                h0 = cvt2h(gelu_f(acc[mf][i0][2]), gelu_f(acc[mf][i0][3]));
                h1 = cvt2h(gelu_f(acc[mf][i1][2]), gelu_f(acc[mf][i1][3]));
                g_efrag[(ra + 8) * 32 + ksIdx * 4 + q] = make_uint2(h0, h1);
            }
        }
    }
}

// ======================================================================
// Edge kernel 2: out = gelu([node[src]|eattr] @ W_ef + b_ef), K=256.
// 256 threads, 8 warps 4(m)x2(n), warp tile 32x64, tile = 128 edges.
// A pre-converted fp16 fragments (g_nfrag ks<8 gather, g_efrag ks>=8);
// Ring-4 A prefetch (distance 3 ksteps ~ DRAM latency).
// ======================================================================
__global__ void __launch_bounds__(256, 1)
edge2_hmma(const int* __restrict__ srcIdx, const float* __restrict__ W,
           const float* __restrict__ bias, float* __restrict__ outp)
{
    extern __shared__ char dyn_smem[];
    uint4* sf = (uint4*)dyn_smem;          // [16][8][32]

    const int tid = threadIdx.x, lane = tid & 31, wid = tid >> 5;
    const int warp_m = wid & 3, warp_n = wid >> 2;
    const int lr = lane >> 2, kc = (lane & 3) * 2, q = lane & 3;

    build_wtable<256>(sf, W, tid, 256);
    __syncthreads();

    const uint4* wfl = sf + (size_t)warp_n * 4 * 32 + lane;

    for (int tile = blockIdx.x; tile < NT_E; tile += gridDim.x) {
        const int mb0 = tile * 128 + warp_m * 32 + lr;   // rows: mb0 + r*8

        uint32_t offN[4];
        #pragma unroll
        for (int r = 0; r < 4; r++)
            offN[r] = (uint32_t)srcIdx[mb0 + r * 8] * 32;
        const uint2* nbase = g_nfrag + q;
        const uint2* ebase = g_efrag + (size_t)mb0 * 32 + q;

        float acc[2][8][4];
        #pragma unroll
        for (int i = 0; i < 8; i++) {
            float2 b = *(const float2*)(bias + (warp_n * 8 + i) * 8 + kc);
            #pragma unroll
            for (int mf = 0; mf < 2; mf++) {
                acc[mf][i][0] = b.x; acc[mf][i][1] = b.y;
                acc[mf][i][2] = b.x; acc[mf][i][3] = b.y;
            }
        }

        uint2 vr[4][4];   // ring-4 x 4 rows
        #define LOADA(KS, BUF)                                                        \
        {                                                                             \
            if ((KS) < 8) {                                                           \
                _Pragma("unroll")                                                     \
                for (int r = 0; r < 4; r++) BUF[r] = nbase[offN[r] + (KS) * 4];       \
            } else {                                                                  \
                _Pragma("unroll")                                                     \
                for (int r = 0; r < 4; r++) BUF[r] = ebase[r * 256 + ((KS) - 8) * 4]; \
            }                                                                         \
        }

        LOADA(0, vr[0]);
        LOADA(1, vr[1]);
        LOADA(2, vr[2]);

        #pragma unroll
        for (int ks = 0; ks < 16; ks++) {
            uint2* cur = vr[ks & 3];
            if (ks + 3 < 16) LOADA(ks + 3, vr[(ks + 3) & 3]);

            uint32_t ah0[4] = {cur[0].x, cur[1].x, cur[0].y, cur[1].y};
            uint32_t ah1[4] = {cur[2].x, cur[3].x, cur[2].y, cur[3].y};

            const uint4* wk = wfl + ks * 256;
            #pragma unroll
            for (int j = 0; j < 4; j++) {
                uint4 f = wk[j * 32];
                mma_f16(acc[0][2 * j + 0], ah0, f.x, f.y);
                mma_f16(acc[0][2 * j + 1], ah0, f.z, f.w);
                mma_f16(acc[1][2 * j + 0], ah1, f.x, f.y);
                mma_f16(acc[1][2 * j + 1], ah1, f.z, f.w);
            }
        }
        #undef LOADA

        // ---- epilogue: gelu + fp32 store to output ----
        #pragma unroll
        for (int mf = 0; mf < 2; mf++) {
            const int ra = mb0 + mf * 16;
            #pragma unroll
            for (int i = 0; i < 8; i++) {
                const int col = (warp_n * 8 + i) * 8 + kc;
                float2 o0, o1;
                o0.x = gelu_f(acc[mf][i][0]); o0.y = gelu_f(acc[mf][i][1]);
                o1.x = gelu_f(acc[mf][i][2]); o1.y = gelu_f(acc[mf][i][3]);
                *(float2*)(outp + (size_t)ra * HH + col)       = o0;
                *(float2*)(outp + (size_t)(ra + 8) * HH + col) = o1;
            }
        }
    }
}

#define SMEM_E1 (12 * 8 * 32 * 16)   // 49,152 B
#define SMEM_E2 (16 * 8 * 32 * 16)   // 65,536 B

// ======================================================================
// launch
// ======================================================================
extern "C" void kernel_launch(void* const* d_in, const int* in_sizes, int n_in,
                              void* d_out, int out_size) {
    const int*   atomic_numbers = (const int*)  d_in[0];
    const float* nde            = (const float*)d_in[1];
    const float* edist          = (const float*)d_in[2];
    const float* edir           = (const float*)d_in[3];
    const int*   charge         = (const int*)  d_in[4];
    const int*   spin           = (const int*)  d_in[5];
    const int*   nbatch         = (const int*)  d_in[6];
    const int*   nsrc           = (const int*)  d_in[7];
    const float* emb_atom       = (const float*)d_in[8];
    const float* W_nd           = (const float*)d_in[9];
    const float* b_nd           = (const float*)d_in[10];
    const float* ln_g           = (const float*)d_in[11];
    const float* ln_b           = (const float*)d_in[12];
    const float* W_node         = (const float*)d_in[13];
    const float* b_node         = (const float*)d_in[14];
    const float* emb_chg        = (const float*)d_in[15];
    const float* emb_spin       = (const float*)d_in[16];
    const float* W_cs           = (const float*)d_in[17];
    const float* b_cs           = (const float*)d_in[18];
    const float* W_edge         = (const float*)d_in[19];
    const float* b_edge         = (const float*)d_in[20];
    const float* W_ef           = (const float*)d_in[21];
    const float* b_ef           = (const float*)d_in[22];
    float* out = (float*)d_out;

    cudaFuncSetAttribute(node_kernel, cudaFuncAttributeMaxDynamicSharedMemorySize, SMEM_NODE);
    cudaFuncSetAttribute(edge1_hmma,  cudaFuncAttributeMaxDynamicSharedMemorySize, SMEM_E1);
    cudaFuncSetAttribute(edge2_hmma,  cudaFuncAttributeMaxDynamicSharedMemorySize, SMEM_E2);

    int nsm = 148;
    cudaDeviceGetAttribute(&nsm, cudaDevAttrMultiProcessorCount, 0);

    cs_kernel<<<NG, 256>>>(charge, spin, emb_chg, emb_spin, W_cs, b_cs);
    node_kernel<<<nsm, 256, SMEM_NODE>>>(atomic_numbers, nde, nbatch, emb_atom,
                                         W_nd, b_nd, ln_g, ln_b, W_node, b_node);
    edge1_hmma<<<nsm, 256, SMEM_E1>>>(edist, edir, W_edge, b_edge);
    edge2_hmma<<<nsm, 256, SMEM_E2>>>(nsrc, W_ef, b_ef, out);
}

// round 16
// speedup vs baseline: 1.1510x; 1.0670x over previous
#include <cuda_runtime.h>
#include <cuda_fp16.h>
#include <cstdint>
#include <cstddef>

// ---------------- problem constants ----------------
#define NN     50000
#define NE     800000
#define NG     32
#define HH     128
#define NDD    16
#define EDD    128
#define DD2D   64

#define NT_E   (NE/256)     // 3125 edge tiles of 256
#define NT_N   (NN/16)      // 3125 node tiles of 16

// ---------------- scratch (device globals: no allocation allowed) ----------------
__device__ float g_cs[NG * HH];
// A operands pre-converted to fp16 mma-fragment form, layout [row][q][ks]:
//   frag[row*32 + q*8 + ks] = {f16x2(k,k+1), f16x2(k+8,k+9)}, k = ks*16 + q*2
// (ks contiguous per q -> uint4 loads cover 2 consecutive ksteps)
__device__ uint2 g_nfrag[(size_t)NN * 32];   //  12.8 MB (node features)
__device__ uint2 g_efrag[(size_t)NE * 32];   // 204.8 MB (edge attrs)

// ---------------- helpers ----------------
__device__ __forceinline__ float gelu_f(float x) {
    return 0.5f * x * (1.0f + erff(x * 0.70710678118654752440f));
}

// pack two f32 -> f16x2 (lo half = a, hi half = b)
__device__ __forceinline__ uint32_t cvt2h(float a, float b) {
    uint32_t r;
    asm("cvt.rn.f16x2.f32 %0, %1, %2;" : "=r"(r) : "f"(b), "f"(a));
    return r;
}

__device__ __forceinline__ void mma_f16(float c[4], const uint32_t a[4],
                                        uint32_t b0, uint32_t b1) {
    asm volatile("mma.sync.aligned.m16n8k16.row.col.f32.f16.f16.f32 "
                 "{%0,%1,%2,%3}, {%4,%5,%6,%7}, {%8,%9}, {%0,%1,%2,%3};"
                 : "+f"(c[0]), "+f"(c[1]), "+f"(c[2]), "+f"(c[3])
                 : "r"(a[0]), "r"(a[1]), "r"(a[2]), "r"(a[3]), "r"(b0), "r"(b1));
}

// 1-pass fp16 W fragment table, two nb packed per uint4:
//   sf[ks][np][lane] = {nb0.b0, nb0.b1, nb1.b0, nb1.b1},  nb0=2*np, nb1=2*np+1
template<int KDIM>
__device__ __forceinline__ void build_wtable(uint4* sf, const float* __restrict__ W,
                                             int tid, int nthreads) {
    constexpr int NKS = KDIM / 16;
    for (int idx = tid; idx < NKS * 8 * 32; idx += nthreads) {
        int li = idx & 31, np = (idx >> 5) & 7, ks = idx >> 8;
        int n0 = (2 * np) * 8 + (li >> 2);
        int n1 = n0 + 8;
        int kg = ks * 16 + (li & 3) * 2;
        uint4 f;
        f.x = cvt2h(W[(size_t)kg * HH + n0],       W[(size_t)(kg + 1) * HH + n0]);
        f.y = cvt2h(W[(size_t)(kg + 8) * HH + n0], W[(size_t)(kg + 9) * HH + n0]);
        f.z = cvt2h(W[(size_t)kg * HH + n1],       W[(size_t)(kg + 1) * HH + n1]);
        f.w = cvt2h(W[(size_t)(kg + 8) * HH + n1], W[(size_t)(kg + 9) * HH + n1]);
        sf[idx] = f;
    }
}

// ======================================================================
// Kernel 0: cs[g] = gelu(concat(emb_chg[charge], emb_spin[spin]) @ W_cs + b_cs)
// 256 threads: k-range split in two halves, smem reduce.
// ======================================================================
__global__ void cs_kernel(const int* __restrict__ charge, const int* __restrict__ spin,
                          const float* __restrict__ emb_chg, const float* __restrict__ emb_spin,
                          const float* __restrict__ W_cs, const float* __restrict__ b_cs) {
    __shared__ float xv[2 * HH];
    __shared__ float part[128];
    int g = blockIdx.x, tid = threadIdx.x;
    int j = tid & 127, h = tid >> 7;
    if (tid < HH) {
        int c = charge[g], s = spin[g];
        xv[tid]      = emb_chg[c * HH + tid];
        xv[HH + tid] = emb_spin[s * HH + tid];
    }
    __syncthreads();
    float acc = 0.f;
    const float* wp = W_cs + (size_t)h * HH * HH + j;
    const float* xp = xv + h * HH;
    #pragma unroll 8
    for (int k = 0; k < HH; k++) acc += xp[k] * wp[k * HH];
    if (h == 1) part[j] = acc;
    __syncthreads();
    if (h == 0)
        g_cs[g * HH + j] = gelu_f(acc + part[j] + b_cs[j]);
}

// ======================================================================
// Kernel 1: node features — embed/LN fp32, GEMM via fp16 HMMA 1-pass.
// Output -> g_nfrag (fp16 fragments, [row][q][ks] layout).
// ======================================================================
#define SXS 264
#define SMEM_NODE (65536 + 16 * SXS * 4)

__global__ void __launch_bounds__(256, 1)
node_kernel(const int* __restrict__ an, const float* __restrict__ nde,
            const int* __restrict__ nbatch,
            const float* __restrict__ emb_atom, const float* __restrict__ W_nd,
            const float* __restrict__ b_nd, const float* __restrict__ ln_g,
            const float* __restrict__ ln_b, const float* __restrict__ W_node,
            const float* __restrict__ b_node) {
    extern __shared__ char dyn_smem[];
    uint4* sfW = (uint4*)dyn_smem;              // [16][8][32]
    float* sx  = (float*)(dyn_smem + 65536);    // [16][SXS]
    __shared__ float smu[16], srs[16];
    const int tid = threadIdx.x, lane = tid & 31, wid = tid >> 5;
    const int lr = lane >> 2, kc = (lane & 3) * 2;

    build_wtable<256>(sfW, W_node, tid, 256);
    __syncthreads();

    for (int t0 = blockIdx.x; t0 < NT_N; t0 += gridDim.x) {
        __syncthreads();   // sx reuse fence
        int n0 = t0 * 16;
        for (int idx = tid; idx < 16 * HH; idx += 256) {
            int n = idx >> 7, j = idx & 127;
            int node = n0 + n;
            float a = emb_atom[an[node] * HH + j];
            float accv = b_nd[j];
            const float* nrow = nde + node * NDD;
            #pragma unroll
            for (int k = 0; k < NDD; k++) accv += nrow[k] * W_nd[k * HH + j];
            sx[n * SXS + j]      = a;
            sx[n * SXS + HH + j] = gelu_f(accv);
        }
        __syncthreads();
        for (int n = wid; n < 16; n += 8) {
            float s1 = 0.f, s2 = 0.f;
            for (int k = lane; k < 256; k += 32) {
                float v = sx[n * SXS + k]; s1 += v; s2 += v * v;
            }
            #pragma unroll
            for (int o = 16; o > 0; o >>= 1) {
                s1 += __shfl_down_sync(0xffffffffu, s1, o);
                s2 += __shfl_down_sync(0xffffffffu, s2, o);
            }
            if (lane == 0) {
                float mu  = s1 * (1.f / 256.f);
                float var = s2 * (1.f / 256.f) - mu * mu;
                smu[n] = mu; srs[n] = rsqrtf(var + 1e-5f);
            }
        }
        __syncthreads();
        for (int idx = tid; idx < 16 * 256; idx += 256) {
            int n = idx >> 8, k = idx & 255;
            sx[n * SXS + k] =
                (sx[n * SXS + k] - smu[n]) * srs[n] * ln_g[k] + ln_b[k];
        }
        __syncthreads();
        // ---- GEMM [16,256]@[256,128]; warp handles nb = 2*wid, 2*wid+1
        {
            float acc[2][4];
            #pragma unroll
            for (int i = 0; i < 2; i++) {
                float2 b = *(const float2*)(b_node + (wid * 2 + i) * 8 + kc);
                acc[i][0] = b.x; acc[i][1] = b.y; acc[i][2] = b.x; acc[i][3] = b.y;
            }
            #pragma unroll
            for (int ks = 0; ks < 16; ks++) {
                const float* x0 = sx + lr * SXS + ks * 16 + kc;
                const float* x1 = x0 + 8 * SXS;
                uint32_t ah[4];
                ah[0] = cvt2h(x0[0], x0[1]);
                ah[1] = cvt2h(x1[0], x1[1]);
                ah[2] = cvt2h(x0[8], x0[9]);
                ah[3] = cvt2h(x1[8], x1[9]);
                uint4 f = sfW[ks * 256 + wid * 32 + lane];
                mma_f16(acc[0], ah, f.x, f.y);
                mma_f16(acc[1], ah, f.z, f.w);
            }
            // epilogue: gelu + cs add, fp16 fragments ([row][q][ks]: q=kc>>1, ks=wid)
            const int node0 = n0 + lr, node1 = node0 + 8;
            const float* cs0 = g_cs + nbatch[node0] * HH;
            const float* cs1 = g_cs + nbatch[node1] * HH;
            const int col0 = wid * 16 + kc;
            const int col1 = col0 + 8;
            const int fi = (kc >> 1) * 8 + wid;
            uint32_t h0, h1;
            h0 = cvt2h(gelu_f(acc[0][0]) + cs0[col0], gelu_f(acc[0][1]) + cs0[col0 + 1]);
            h1 = cvt2h(gelu_f(acc[1][0]) + cs0[col1], gelu_f(acc[1][1]) + cs0[col1 + 1]);
            g_nfrag[(size_t)node0 * 32 + fi] = make_uint2(h0, h1);
            h0 = cvt2h(gelu_f(acc[0][2]) + cs1[col0], gelu_f(acc[0][3]) + cs1[col0 + 1]);
            h1 = cvt2h(gelu_f(acc[1][2]) + cs1[col1], gelu_f(acc[1][3]) + cs1[col1 + 1]);
            g_nfrag[(size_t)node1 * 32 + fi] = make_uint2(h0, h1);
        }
    }
}

// ======================================================================
// Edge kernel 1: eattr = gelu([edist|edir] @ W_edge + b_edge), K=192.
// 512 threads, 16 warps 8(m)x2(n), warp tile 32x64, tile = 256 edges.
// fp16 1-pass; A prefetch depth 2. Output -> g_efrag ([row][q][ks]).
// ======================================================================
__global__ void __launch_bounds__(512, 1)
edge1_hmma(const float* __restrict__ P0, const float* __restrict__ P1,
           const float* __restrict__ W, const float* __restrict__ bias)
{
    constexpr int NKS = 12;
    extern __shared__ char dyn_smem[];
    uint4* sf = (uint4*)dyn_smem;          // [12][8][32]

    const int tid = threadIdx.x, lane = tid & 31, wid = tid >> 5;
    const int warp_m = wid & 7, warp_n = wid >> 3;
    const int lr = lane >> 2, kc = (lane & 3) * 2, q = lane & 3;

    build_wtable<192>(sf, W, tid, 512);
    __syncthreads();

    const uint4* wfl = sf + (size_t)warp_n * 4 * 32 + lane;

    for (int tile = blockIdx.x; tile < NT_E; tile += gridDim.x) {
        const int e0 = tile * 256;
        const int mb0 = e0 + warp_m * 32 + lr;   // rows: mb0 + r*8, r=0..3
        const float* pA = P0 + (size_t)mb0 * EDD + kc;
        const float* pB = P1 + (size_t)mb0 * DD2D + kc;

        float acc[2][8][4];
        #pragma unroll
        for (int i = 0; i < 8; i++) {
            float2 b = *(const float2*)(bias + (warp_n * 8 + i) * 8 + kc);
            #pragma unroll
            for (int mf = 0; mf < 2; mf++) {
                acc[mf][i][0] = b.x; acc[mf][i][1] = b.y;
                acc[mf][i][2] = b.x; acc[mf][i][3] = b.y;
            }
        }

        float2 v0[4][2], v1[4][2];
        #define LOADA(KG, VV)                                                      \
        {                                                                          \
            _Pragma("unroll")                                                      \
            for (int r = 0; r < 4; r++) {                                          \
                const float* qq = ((KG) < 128) ? pA + r * 8 * EDD + (KG)           \
                                               : pB + r * 8 * DD2D + ((KG) - 128); \
                (VV)[r][0] = *(const float2*)qq;                                   \
                (VV)[r][1] = *(const float2*)(qq + 8);                             \
            }                                                                      \
        }

        LOADA(0, v0);
        LOADA(16, v1);

        #pragma unroll
        for (int ks = 0; ks < NKS; ks++) {
            float2 (*cur)[2] = (ks & 1) ? v1 : v0;
            uint32_t ah0[4], ah1[4];
            ah0[0] = cvt2h(cur[0][0].x, cur[0][0].y);
            ah0[1] = cvt2h(cur[1][0].x, cur[1][0].y);
            ah0[2] = cvt2h(cur[0][1].x, cur[0][1].y);
            ah0[3] = cvt2h(cur[1][1].x, cur[1][1].y);
            ah1[0] = cvt2h(cur[2][0].x, cur[2][0].y);
            ah1[1] = cvt2h(cur[3][0].x, cur[3][0].y);
            ah1[2] = cvt2h(cur[2][1].x, cur[2][1].y);
            ah1[3] = cvt2h(cur[3][1].x, cur[3][1].y);
            if (ks + 2 < NKS) {
                if (ks & 1) { LOADA((ks + 2) * 16, v1); }
                else        { LOADA((ks + 2) * 16, v0); }
            }

            const uint4* wk = wfl + ks * 256;
            #pragma unroll
            for (int j = 0; j < 4; j++) {
                uint4 f = wk[j * 32];
                mma_f16(acc[0][2 * j + 0], ah0, f.x, f.y);
                mma_f16(acc[0][2 * j + 1], ah0, f.z, f.w);
                mma_f16(acc[1][2 * j + 0], ah1, f.x, f.y);
                mma_f16(acc[1][2 * j + 1], ah1, f.z, f.w);
            }
        }
        #undef LOADA

        // ---- epilogue: gelu, fp16 fragments ([row][q][ks]: ks = warp_n*4 + j)
        #pragma unroll
        for (int mf = 0; mf < 2; mf++) {
            const size_t ra = (size_t)(mb0 + mf * 16);
            #pragma unroll
            for (int j = 0; j < 4; j++) {
                const int i0 = 2 * j, i1 = 2 * j + 1;
                const int fi = q * 8 + warp_n * 4 + j;
                uint32_t h0, h1;
                h0 = cvt2h(gelu_f(acc[mf][i0][0]), gelu_f(acc[mf][i0][1]));
                h1 = cvt2h(gelu_f(acc[mf][i1][0]), gelu_f(acc[mf][i1][1]));
                g_efrag[ra * 32 + fi] = make_uint2(h0, h1);
                h0 = cvt2h(gelu_f(acc[mf][i0][2]), gelu_f(acc[mf][i0][3]));
                h1 = cvt2h(gelu_f(acc[mf][i1][2]), gelu_f(acc[mf][i1][3]));
                g_efrag[(ra + 8) * 32 + fi] = make_uint2(h0, h1);
            }
        }
    }
}

// ======================================================================
// Edge kernel 2: out = gelu([node[src]|eattr] @ W_ef + b_ef), K=256.
// A pre-converted fp16 fragments in [row][q][ks] layout:
// uint4 loads cover 2 ksteps -> 4x LDG.128 per PAIR (was 8x LDG.64),
// pair-level double buffer (prefetch distance 2 ksteps).
// 512 threads, 16 warps 8(m)x2(n), warp tile 32x64, tile = 256 edges.
// ======================================================================
__global__ void __launch_bounds__(512, 1)
edge2_hmma(const int* __restrict__ srcIdx, const float* __restrict__ W,
           const float* __restrict__ bias, float* __restrict__ outp)
{
    extern __shared__ char dyn_smem[];
    uint4* sf = (uint4*)dyn_smem;          // [16][8][32]

    const int tid = threadIdx.x, lane = tid & 31, wid = tid >> 5;
    const int warp_m = wid & 7, warp_n = wid >> 3;
    const int lr = lane >> 2, kc = (lane & 3) * 2, q = lane & 3;

    build_wtable<256>(sf, W, tid, 512);
    __syncthreads();

    const uint4* wfl = sf + (size_t)warp_n * 4 * 32 + lane;
    const int q8 = q * 8;

    for (int tile = blockIdx.x; tile < NT_E; tile += gridDim.x) {
        const int e0 = tile * 256;
        const int mb0 = e0 + warp_m * 32 + lr;   // rows: mb0 + r*8, r=0..3

        uint32_t offN[4];
        #pragma unroll
        for (int r = 0; r < 4; r++)
            offN[r] = (uint32_t)srcIdx[mb0 + r * 8] * 32 + q8;
        const uint2* nb = g_nfrag;
        const uint2* eb = g_efrag + (size_t)mb0 * 32 + q8;

        float acc[2][8][4];
        #pragma unroll
        for (int i = 0; i < 8; i++) {
            float2 b = *(const float2*)(bias + (warp_n * 8 + i) * 8 + kc);
            #pragma unroll
            for (int mf = 0; mf < 2; mf++) {
                acc[mf][i][0] = b.x; acc[mf][i][1] = b.y;
                acc[mf][i][2] = b.x; acc[mf][i][3] = b.y;
            }
        }

        // pair P covers ksteps 2P, 2P+1; P<4 from nfrag gather, P>=4 from efrag
        uint4 va[4], vb[4];
        #define LOADP(P, BUF)                                                          \
        {                                                                              \
            if ((P) < 4) {                                                             \
                _Pragma("unroll")                                                      \
                for (int r = 0; r < 4; r++)                                            \
                    BUF[r] = *(const uint4*)(nb + offN[r] + (P) * 2);                  \
            } else {                                                                   \
                _Pragma("unroll")                                                      \
                for (int r = 0; r < 4; r++)                                            \
                    BUF[r] = *(const uint4*)(eb + r * 256 + ((P) - 4) * 2);            \
            }                                                                          \
        }

        LOADP(0, va);

        #pragma unroll
        for (int p = 0; p < 8; p++) {
            uint4* cur = (p & 1) ? vb : va;
            uint4* nxt = (p & 1) ? va : vb;
            if (p + 1 < 8) LOADP(p + 1, nxt);

            // kstep 2p: a-operands from .x/.y halves (register selection)
            {
                uint32_t ah0[4] = {cur[0].x, cur[1].x, cur[0].y, cur[1].y};
                uint32_t ah1[4] = {cur[2].x, cur[3].x, cur[2].y, cur[3].y};
                const uint4* wk = wfl + (2 * p) * 256;
                #pragma unroll
                for (int j = 0; j < 4; j++) {
                    uint4 f = wk[j * 32];
                    mma_f16(acc[0][2 * j + 0], ah0, f.x, f.y);
                    mma_f16(acc[0][2 * j + 1], ah0, f.z, f.w);
                    mma_f16(acc[1][2 * j + 0], ah1, f.x, f.y);
                    mma_f16(acc[1][2 * j + 1], ah1, f.z, f.w);
                }
            }
            // kstep 2p+1: a-operands from .z/.w halves
            {
                uint32_t ah0[4] = {cur[0].z, cur[1].z, cur[0].w, cur[1].w};
                uint32_t ah1[4] = {cur[2].z, cur[3].z, cur[2].w, cur[3].w};
                const uint4* wk = wfl + (2 * p + 1) * 256;
                #pragma unroll
                for (int j = 0; j < 4; j++) {
                    uint4 f = wk[j * 32];
                    mma_f16(acc[0][2 * j + 0], ah0, f.x, f.y);
                    mma_f16(acc[0][2 * j + 1], ah0, f.z, f.w);
                    mma_f16(acc[1][2 * j + 0], ah1, f.x, f.y);
                    mma_f16(acc[1][2 * j + 1], ah1, f.z, f.w);
                }
            }
        }
        #undef LOADP

        // ---- epilogue: gelu + fp32 store to output ----
        #pragma unroll
        for (int mf = 0; mf < 2; mf++) {
            const int ra = mb0 + mf * 16;
            #pragma unroll
            for (int i = 0; i < 8; i++) {
                const int col = (warp_n * 8 + i) * 8 + kc;
                float2 o0, o1;
                o0.x = gelu_f(acc[mf][i][0]); o0.y = gelu_f(acc[mf][i][1]);
                o1.x = gelu_f(acc[mf][i][2]); o1.y = gelu_f(acc[mf][i][3]);
                *(float2*)(outp + (size_t)ra * HH + col)       = o0;
                *(float2*)(outp + (size_t)(ra + 8) * HH + col) = o1;
            }
        }
    }
}

#define SMEM_E1 (12 * 8 * 32 * 16)   // 49,152 B
#define SMEM_E2 (16 * 8 * 32 * 16)   // 65,536 B

// ======================================================================
// launch
// ======================================================================
extern "C" void kernel_launch(void* const* d_in, const int* in_sizes, int n_in,
                              void* d_out, int out_size) {
    const int*   atomic_numbers = (const int*)  d_in[0];
    const float* nde            = (const float*)d_in[1];
    const float* edist          = (const float*)d_in[2];
    const float* edir           = (const float*)d_in[3];
    const int*   charge         = (const int*)  d_in[4];
    const int*   spin           = (const int*)  d_in[5];
    const int*   nbatch         = (const int*)  d_in[6];
    const int*   nsrc           = (const int*)  d_in[7];
    const float* emb_atom       = (const float*)d_in[8];
    const float* W_nd           = (const float*)d_in[9];
    const float* b_nd           = (const float*)d_in[10];
    const float* ln_g           = (const float*)d_in[11];
    const float* ln_b           = (const float*)d_in[12];
    const float* W_node         = (const float*)d_in[13];
    const float* b_node         = (const float*)d_in[14];
    const float* emb_chg        = (const float*)d_in[15];
    const float* emb_spin       = (const float*)d_in[16];
    const float* W_cs           = (const float*)d_in[17];
    const float* b_cs           = (const float*)d_in[18];
    const float* W_edge         = (const float*)d_in[19];
    const float* b_edge         = (const float*)d_in[20];
    const float* W_ef           = (const float*)d_in[21];
    const float* b_ef           = (const float*)d_in[22];
    float* out = (float*)d_out;

    cudaFuncSetAttribute(node_kernel, cudaFuncAttributeMaxDynamicSharedMemorySize, SMEM_NODE);
    cudaFuncSetAttribute(edge1_hmma,  cudaFuncAttributeMaxDynamicSharedMemorySize, SMEM_E1);
    cudaFuncSetAttribute(edge2_hmma,  cudaFuncAttributeMaxDynamicSharedMemorySize, SMEM_E2);

    int nsm = 148;
    cudaDeviceGetAttribute(&nsm, cudaDevAttrMultiProcessorCount, 0);

    cs_kernel<<<NG, 256>>>(charge, spin, emb_chg, emb_spin, W_cs, b_cs);
    node_kernel<<<nsm, 256, SMEM_NODE>>>(atomic_numbers, nde, nbatch, emb_atom,
                                         W_nd, b_nd, ln_g, ln_b, W_node, b_node);
    edge1_hmma<<<nsm, 512, SMEM_E1>>>(edist, edir, W_edge, b_edge);
    edge2_hmma<<<nsm, 512, SMEM_E2>>>(nsrc, W_ef, b_ef, out);
}

// round 17
// speedup vs baseline: 1.2427x; 1.0797x over previous
#include <cuda_runtime.h>
#include <cuda_fp16.h>
#include <cstdint>
#include <cstddef>

// ---------------- problem constants ----------------
#define NN     50000
#define NE     800000
#define NG     32
#define HH     128
#define NDD    16
#define EDD    128
#define DD2D   64

#define NT_E   (NE/256)     // 3125 edge tiles of 256
#define NT_N   (NN/16)      // 3125 node tiles of 16

// ---------------- scratch (device globals: no allocation allowed) ----------------
__device__ float g_cs[NG * HH];
// A operands pre-converted to fp16 mma-fragment form, PAIR layout:
//   frag[row*32 + (ks>>1)*8 + q*2 + (ks&1)] = {f16x2(k,k+1), f16x2(k+8,k+9)},
//   k = ks*16 + q*2.  Readers: uint4 @ (P*8+q*2) covers ksteps 2P,2P+1 and is
//   quad-contiguous (64B); writers: 2 aligned uint4 per thread, quad-contiguous.
__device__ uint2 g_nfrag[(size_t)NN * 32];   //  12.8 MB (node features)
__device__ uint2 g_efrag[(size_t)NE * 32];   // 204.8 MB (edge attrs)

// ---------------- helpers ----------------
__device__ __forceinline__ float gelu_f(float x) {
    return 0.5f * x * (1.0f + erff(x * 0.70710678118654752440f));
}

// pack two f32 -> f16x2 (lo half = a, hi half = b)
__device__ __forceinline__ uint32_t cvt2h(float a, float b) {
    uint32_t r;
    asm("cvt.rn.f16x2.f32 %0, %1, %2;" : "=r"(r) : "f"(b), "f"(a));
    return r;
}

__device__ __forceinline__ void mma_f16(float c[4], const uint32_t a[4],
                                        uint32_t b0, uint32_t b1) {
    asm volatile("mma.sync.aligned.m16n8k16.row.col.f32.f16.f16.f32 "
                 "{%0,%1,%2,%3}, {%4,%5,%6,%7}, {%8,%9}, {%0,%1,%2,%3};"
                 : "+f"(c[0]), "+f"(c[1]), "+f"(c[2]), "+f"(c[3])
                 : "r"(a[0]), "r"(a[1]), "r"(a[2]), "r"(a[3]), "r"(b0), "r"(b1));
}

// 1-pass fp16 W fragment table, two nb packed per uint4:
//   sf[ks][np][lane] = {nb0.b0, nb0.b1, nb1.b0, nb1.b1},  nb0=2*np, nb1=2*np+1
template<int KDIM>
__device__ __forceinline__ void build_wtable(uint4* sf, const float* __restrict__ W,
                                             int tid, int nthreads) {
    constexpr int NKS = KDIM / 16;
    for (int idx = tid; idx < NKS * 8 * 32; idx += nthreads) {
        int li = idx & 31, np = (idx >> 5) & 7, ks = idx >> 8;
        int n0 = (2 * np) * 8 + (li >> 2);
        int n1 = n0 + 8;
        int kg = ks * 16 + (li & 3) * 2;
        uint4 f;
        f.x = cvt2h(W[(size_t)kg * HH + n0],       W[(size_t)(kg + 1) * HH + n0]);
        f.y = cvt2h(W[(size_t)(kg + 8) * HH + n0], W[(size_t)(kg + 9) * HH + n0]);
        f.z = cvt2h(W[(size_t)kg * HH + n1],       W[(size_t)(kg + 1) * HH + n1]);
        f.w = cvt2h(W[(size_t)(kg + 8) * HH + n1], W[(size_t)(kg + 9) * HH + n1]);
        sf[idx] = f;
    }
}

// ======================================================================
// Kernel 0: cs[g] = gelu(concat(emb_chg[charge], emb_spin[spin]) @ W_cs + b_cs)
// 256 threads: k-range split in two halves, smem reduce.
// ======================================================================
__global__ void cs_kernel(const int* __restrict__ charge, const int* __restrict__ spin,
                          const float* __restrict__ emb_chg, const float* __restrict__ emb_spin,
                          const float* __restrict__ W_cs, const float* __restrict__ b_cs) {
    __shared__ float xv[2 * HH];
    __shared__ float part[128];
    int g = blockIdx.x, tid = threadIdx.x;
    int j = tid & 127, h = tid >> 7;
    if (tid < HH) {
        int c = charge[g], s = spin[g];
        xv[tid]      = emb_chg[c * HH + tid];
        xv[HH + tid] = emb_spin[s * HH + tid];
    }
    __syncthreads();
    float acc = 0.f;
    const float* wp = W_cs + (size_t)h * HH * HH + j;
    const float* xp = xv + h * HH;
    #pragma unroll 8
    for (int k = 0; k < HH; k++) acc += xp[k] * wp[k * HH];
    if (h == 1) part[j] = acc;
    __syncthreads();
    if (h == 0)
        g_cs[g * HH + j] = gelu_f(acc + part[j] + b_cs[j]);
}

// ======================================================================
// Kernel 1: node features — embed/LN fp32, GEMM via fp16 HMMA 1-pass.
// Output -> g_nfrag (fp16 fragments, pair layout).
// ======================================================================
#define SXS 264
#define SMEM_NODE (65536 + 16 * SXS * 4)

__global__ void __launch_bounds__(256, 1)
node_kernel(const int* __restrict__ an, const float* __restrict__ nde,
            const int* __restrict__ nbatch,
            const float* __restrict__ emb_atom, const float* __restrict__ W_nd,
            const float* __restrict__ b_nd, const float* __restrict__ ln_g,
            const float* __restrict__ ln_b, const float* __restrict__ W_node,
            const float* __restrict__ b_node) {
    extern __shared__ char dyn_smem[];
    uint4* sfW = (uint4*)dyn_smem;              // [16][8][32]
    float* sx  = (float*)(dyn_smem + 65536);    // [16][SXS]
    __shared__ float smu[16], srs[16];
    const int tid = threadIdx.x, lane = tid & 31, wid = tid >> 5;
    const int lr = lane >> 2, kc = (lane & 3) * 2;

    build_wtable<256>(sfW, W_node, tid, 256);
    __syncthreads();

    for (int t0 = blockIdx.x; t0 < NT_N; t0 += gridDim.x) {
        __syncthreads();   // sx reuse fence
        int n0 = t0 * 16;
        for (int idx = tid; idx < 16 * HH; idx += 256) {
            int n = idx >> 7, j = idx & 127;
            int node = n0 + n;
            float a = emb_atom[an[node] * HH + j];
            float accv = b_nd[j];
            const float* nrow = nde + node * NDD;
            #pragma unroll
            for (int k = 0; k < NDD; k++) accv += nrow[k] * W_nd[k * HH + j];
            sx[n * SXS + j]      = a;
            sx[n * SXS + HH + j] = gelu_f(accv);
        }
        __syncthreads();
        for (int n = wid; n < 16; n += 8) {
            float s1 = 0.f, s2 = 0.f;
            for (int k = lane; k < 256; k += 32) {
                float v = sx[n * SXS + k]; s1 += v; s2 += v * v;
            }
            #pragma unroll
            for (int o = 16; o > 0; o >>= 1) {
                s1 += __shfl_down_sync(0xffffffffu, s1, o);
                s2 += __shfl_down_sync(0xffffffffu, s2, o);
            }
            if (lane == 0) {
                float mu  = s1 * (1.f / 256.f);
                float var = s2 * (1.f / 256.f) - mu * mu;
                smu[n] = mu; srs[n] = rsqrtf(var + 1e-5f);
            }
        }
        __syncthreads();
        for (int idx = tid; idx < 16 * 256; idx += 256) {
            int n = idx >> 8, k = idx & 255;
            sx[n * SXS + k] =
                (sx[n * SXS + k] - smu[n]) * srs[n] * ln_g[k] + ln_b[k];
        }
        __syncthreads();
        // ---- GEMM [16,256]@[256,128]; warp handles nb = 2*wid, 2*wid+1
        {
            float acc[2][4];
            #pragma unroll
            for (int i = 0; i < 2; i++) {
                float2 b = *(const float2*)(b_node + (wid * 2 + i) * 8 + kc);
                acc[i][0] = b.x; acc[i][1] = b.y; acc[i][2] = b.x; acc[i][3] = b.y;
            }
            #pragma unroll
            for (int ks = 0; ks < 16; ks++) {
                const float* x0 = sx + lr * SXS + ks * 16 + kc;
                const float* x1 = x0 + 8 * SXS;
                uint32_t ah[4];
                ah[0] = cvt2h(x0[0], x0[1]);
                ah[1] = cvt2h(x1[0], x1[1]);
                ah[2] = cvt2h(x0[8], x0[9]);
                ah[3] = cvt2h(x1[8], x1[9]);
                uint4 f = sfW[ks * 256 + wid * 32 + lane];
                mma_f16(acc[0], ah, f.x, f.y);
                mma_f16(acc[1], ah, f.z, f.w);
            }
            // epilogue: gelu + cs add, fp16 fragments (pair layout: ks=wid, q=kc>>1)
            const int node0 = n0 + lr, node1 = node0 + 8;
            const float* cs0 = g_cs + nbatch[node0] * HH;
            const float* cs1 = g_cs + nbatch[node1] * HH;
            const int col0 = wid * 16 + kc;
            const int col1 = col0 + 8;
            const int fi = (wid >> 1) * 8 + (kc >> 1) * 2 + (wid & 1);
            uint32_t h0, h1;
            h0 = cvt2h(gelu_f(acc[0][0]) + cs0[col0], gelu_f(acc[0][1]) + cs0[col0 + 1]);
            h1 = cvt2h(gelu_f(acc[1][0]) + cs0[col1], gelu_f(acc[1][1]) + cs0[col1 + 1]);
            g_nfrag[(size_t)node0 * 32 + fi] = make_uint2(h0, h1);
            h0 = cvt2h(gelu_f(acc[0][2]) + cs1[col0], gelu_f(acc[0][3]) + cs1[col0 + 1]);
            h1 = cvt2h(gelu_f(acc[1][2]) + cs1[col1], gelu_f(acc[1][3]) + cs1[col1 + 1]);
            g_nfrag[(size_t)node1 * 32 + fi] = make_uint2(h0, h1);
        }
    }
}

// ======================================================================
// Edge kernel 1: eattr = gelu([edist|edir] @ W_edge + b_edge), K=192.
// 512 threads, 16 warps 8(m)x2(n), warp tile 32x64, tile = 256 edges.
// fp16 1-pass; A prefetch depth 2. Output -> g_efrag (pair layout,
// two aligned uint4 stores per thread per row — fully coalesced).
// ======================================================================
__global__ void __launch_bounds__(512, 1)
edge1_hmma(const float* __restrict__ P0, const float* __restrict__ P1,
           const float* __restrict__ W, const float* __restrict__ bias)
{
    constexpr int NKS = 12;
    extern __shared__ char dyn_smem[];
    uint4* sf = (uint4*)dyn_smem;          // [12][8][32]

    const int tid = threadIdx.x, lane = tid & 31, wid = tid >> 5;
    const int warp_m = wid & 7, warp_n = wid >> 3;
    const int lr = lane >> 2, kc = (lane & 3) * 2, q = lane & 3;

    build_wtable<192>(sf, W, tid, 512);
    __syncthreads();

    const uint4* wfl = sf + (size_t)warp_n * 4 * 32 + lane;

    for (int tile = blockIdx.x; tile < NT_E; tile += gridDim.x) {
        const int e0 = tile * 256;
        const int mb0 = e0 + warp_m * 32 + lr;   // rows: mb0 + r*8, r=0..3
        const float* pA = P0 + (size_t)mb0 * EDD + kc;
        const float* pB = P1 + (size_t)mb0 * DD2D + kc;

        float acc[2][8][4];
        #pragma unroll
        for (int i = 0; i < 8; i++) {
            float2 b = *(const float2*)(bias + (warp_n * 8 + i) * 8 + kc);
            #pragma unroll
            for (int mf = 0; mf < 2; mf++) {
                acc[mf][i][0] = b.x; acc[mf][i][1] = b.y;
                acc[mf][i][2] = b.x; acc[mf][i][3] = b.y;
            }
        }

        float2 v0[4][2], v1[4][2];
        #define LOADA(KG, VV)                                                      \
        {                                                                          \
            _Pragma("unroll")                                                      \
            for (int r = 0; r < 4; r++) {                                          \
                const float* qq = ((KG) < 128) ? pA + r * 8 * EDD + (KG)           \
                                               : pB + r * 8 * DD2D + ((KG) - 128); \
                (VV)[r][0] = *(const float2*)qq;                                   \
                (VV)[r][1] = *(const float2*)(qq + 8);                             \
            }                                                                      \
        }

        LOADA(0, v0);
        LOADA(16, v1);

        #pragma unroll
        for (int ks = 0; ks < NKS; ks++) {
            float2 (*cur)[2] = (ks & 1) ? v1 : v0;
            uint32_t ah0[4], ah1[4];
            ah0[0] = cvt2h(cur[0][0].x, cur[0][0].y);
            ah0[1] = cvt2h(cur[1][0].x, cur[1][0].y);
            ah0[2] = cvt2h(cur[0][1].x, cur[0][1].y);
            ah0[3] = cvt2h(cur[1][1].x, cur[1][1].y);
            ah1[0] = cvt2h(cur[2][0].x, cur[2][0].y);
            ah1[1] = cvt2h(cur[3][0].x, cur[3][0].y);
            ah1[2] = cvt2h(cur[2][1].x, cur[2][1].y);
            ah1[3] = cvt2h(cur[3][1].x, cur[3][1].y);
            if (ks + 2 < NKS) {
                if (ks & 1) { LOADA((ks + 2) * 16, v1); }
                else        { LOADA((ks + 2) * 16, v0); }
            }

            const uint4* wk = wfl + ks * 256;
            #pragma unroll
            for (int j = 0; j < 4; j++) {
                uint4 f = wk[j * 32];
                mma_f16(acc[0][2 * j + 0], ah0, f.x, f.y);
                mma_f16(acc[0][2 * j + 1], ah0, f.z, f.w);
                mma_f16(acc[1][2 * j + 0], ah1, f.x, f.y);
                mma_f16(acc[1][2 * j + 1], ah1, f.z, f.w);
            }
        }
        #undef LOADA

        // ---- epilogue: gelu, fp16 fragments, pair layout.
        // element j (=0..3) -> fi = (warp_n*2 + (j>>1))*8 + q*2 + (j&1);
        // j pairs (0,1) and (2,3) merge into aligned uint4 stores.
        #pragma unroll
        for (int mf = 0; mf < 2; mf++) {
            #pragma unroll
            for (int half = 0; half < 2; half++) {
                const size_t ra = (size_t)(mb0 + mf * 16 + half * 8);
                const int c0 = half * 2, c1 = half * 2 + 1;
                uint2* dst = g_efrag + ra * 32 + q * 2;
                #pragma unroll
                for (int jj = 0; jj < 2; jj++) {
                    uint4 st;
                    st.x = cvt2h(gelu_f(acc[mf][4 * jj + 0][c0]), gelu_f(acc[mf][4 * jj + 0][c1]));
                    st.y = cvt2h(gelu_f(acc[mf][4 * jj + 1][c0]), gelu_f(acc[mf][4 * jj + 1][c1]));
                    st.z = cvt2h(gelu_f(acc[mf][4 * jj + 2][c0]), gelu_f(acc[mf][4 * jj + 2][c1]));
                    st.w = cvt2h(gelu_f(acc[mf][4 * jj + 3][c0]), gelu_f(acc[mf][4 * jj + 3][c1]));
                    *(uint4*)(dst + (warp_n * 2 + jj) * 8) = st;
                }
            }
        }
    }
}

// ======================================================================
// Edge kernel 2: out = gelu([node[src]|eattr] @ W_ef + b_ef), K=256.
// Pair layout. Phase-split prefetch:
//   - efrag (DRAM, ~577cyc): pairs 0-1 issued at tile start (consumed after
//     the node phase, ~1500cyc later); pairs 2-3 two pairs ahead.
//   - node gather (L2-resident table, ~240cyc): uint2 kstep double-buffer.
// 512 threads, 16 warps 8(m)x2(n), warp tile 32x64, tile = 256 edges.
// ======================================================================
__global__ void __launch_bounds__(512, 1)
edge2_hmma(const int* __restrict__ srcIdx, const float* __restrict__ W,
           const float* __restrict__ bias, float* __restrict__ outp)
{
    extern __shared__ char dyn_smem[];
    uint4* sf = (uint4*)dyn_smem;          // [16][8][32]

    const int tid = threadIdx.x, lane = tid & 31, wid = tid >> 5;
    const int warp_m = wid & 7, warp_n = wid >> 3;
    const int lr = lane >> 2, kc = (lane & 3) * 2, q = lane & 3;

    build_wtable<256>(sf, W, tid, 512);
    __syncthreads();

    const uint4* wfl = sf + (size_t)warp_n * 4 * 32 + lane;

    #define MMABLK(KS, A0, A1)                                           \
    {                                                                    \
        const uint4* wk = wfl + (KS) * 256;                              \
        _Pragma("unroll")                                                \
        for (int j = 0; j < 4; j++) {                                    \
            uint4 f = wk[j * 32];                                        \
            mma_f16(acc[0][2 * j + 0], A0, f.x, f.y);                    \
            mma_f16(acc[0][2 * j + 1], A0, f.z, f.w);                    \
            mma_f16(acc[1][2 * j + 0], A1, f.x, f.y);                    \
            mma_f16(acc[1][2 * j + 1], A1, f.z, f.w);                    \
        }                                                                \
    }

    for (int tile = blockIdx.x; tile < NT_E; tile += gridDim.x) {
        const int e0 = tile * 256;
        const int mb0 = e0 + warp_m * 32 + lr;   // rows: mb0 + r*8, r=0..3

        uint32_t offN[4];
        #pragma unroll
        for (int r = 0; r < 4; r++)
            offN[r] = (uint32_t)srcIdx[mb0 + r * 8] * 32 + q * 2;
        const uint2* nb = g_nfrag;
        const uint2* eb = g_efrag + (size_t)mb0 * 32 + q * 2;

        // ---- efrag pair prefetch (pairs 0,1 now; 2,3 two pairs ahead) ----
        uint4 vf0[4], vf1[4];
        #define LOADF(P, BUF)                                                  \
        {                                                                      \
            _Pragma("unroll")                                                  \
            for (int r = 0; r < 4; r++)                                        \
                BUF[r] = *(const uint4*)(eb + r * 256 + (P) * 8);              \
        }
        LOADF(0, vf0);
        LOADF(1, vf1);

        float acc[2][8][4];
        #pragma unroll
        for (int i = 0; i < 8; i++) {
            float2 b = *(const float2*)(bias + (warp_n * 8 + i) * 8 + kc);
            #pragma unroll
            for (int mf = 0; mf < 2; mf++) {
                acc[mf][i][0] = b.x; acc[mf][i][1] = b.y;
                acc[mf][i][2] = b.x; acc[mf][i][3] = b.y;
            }
        }

        // ---- node phase: ksteps 0..7, uint2 double-buffer ----
        uint2 na[4], nbuf[4];
        #define LOADN(KS, BUF)                                                 \
        {                                                                      \
            _Pragma("unroll")                                                  \
            for (int r = 0; r < 4; r++)                                        \
                BUF[r] = nb[offN[r] + ((KS) >> 1) * 8 + ((KS) & 1)];           \
        }
        LOADN(0, na);

        #pragma unroll
        for (int ks = 0; ks < 8; ks++) {
            uint2* cur = (ks & 1) ? nbuf : na;
            uint2* nxt = (ks & 1) ? na : nbuf;
            if (ks + 1 < 8) LOADN(ks + 1, nxt);
            uint32_t ah0[4] = {cur[0].x, cur[1].x, cur[0].y, cur[1].y};
            uint32_t ah1[4] = {cur[2].x, cur[3].x, cur[2].y, cur[3].y};
            MMABLK(ks, ah0, ah1);
        }

        // ---- eattr phase: pairs 0..3 (ksteps 8..15) ----
        #pragma unroll
        for (int p = 0; p < 4; p++) {
            uint4* cur = (p & 1) ? vf1 : vf0;
            // extract both ksteps' a-operands, then refill the buffer early
            uint32_t e0a[4] = {cur[0].x, cur[1].x, cur[0].y, cur[1].y};
            uint32_t e0b[4] = {cur[2].x, cur[3].x, cur[2].y, cur[3].y};
            uint32_t e1a[4] = {cur[0].z, cur[1].z, cur[0].w, cur[1].w};
            uint32_t e1b[4] = {cur[2].z, cur[3].z, cur[2].w, cur[3].w};
            if (p + 2 < 4) LOADF(p + 2, cur);
            MMABLK(8 + 2 * p, e0a, e0b);
            MMABLK(9 + 2 * p, e1a, e1b);
        }
        #undef LOADF
        #undef LOADN

        // ---- epilogue: gelu + fp32 store to output ----
        #pragma unroll
        for (int mf = 0; mf < 2; mf++) {
            const int ra = mb0 + mf * 16;
            #pragma unroll
            for (int i = 0; i < 8; i++) {
                const int col = (warp_n * 8 + i) * 8 + kc;
                float2 o0, o1;
                o0.x = gelu_f(acc[mf][i][0]); o0.y = gelu_f(acc[mf][i][1]);
                o1.x = gelu_f(acc[mf][i][2]); o1.y = gelu_f(acc[mf][i][3]);
                *(float2*)(outp + (size_t)ra * HH + col)       = o0;
                *(float2*)(outp + (size_t)(ra + 8) * HH + col) = o1;
            }
        }
    }
    #undef MMABLK
}

#define SMEM_E1 (12 * 8 * 32 * 16)   // 49,152 B
#define SMEM_E2 (16 * 8 * 32 * 16)   // 65,536 B

// ======================================================================
// launch
// ======================================================================
extern "C" void kernel_launch(void* const* d_in, const int* in_sizes, int n_in,
                              void* d_out, int out_size) {
    const int*   atomic_numbers = (const int*)  d_in[0];
    const float* nde            = (const float*)d_in[1];
    const float* edist          = (const float*)d_in[2];
    const float* edir           = (const float*)d_in[3];
    const int*   charge         = (const int*)  d_in[4];
    const int*   spin           = (const int*)  d_in[5];
    const int*   nbatch         = (const int*)  d_in[6];
    const int*   nsrc           = (const int*)  d_in[7];
    const float* emb_atom       = (const float*)d_in[8];
    const float* W_nd           = (const float*)d_in[9];
    const float* b_nd           = (const float*)d_in[10];
    const float* ln_g           = (const float*)d_in[11];
    const float* ln_b           = (const float*)d_in[12];
    const float* W_node         = (const float*)d_in[13];
    const float* b_node         = (const float*)d_in[14];
    const float* emb_chg        = (const float*)d_in[15];
    const float* emb_spin       = (const float*)d_in[16];
    const float* W_cs           = (const float*)d_in[17];
    const float* b_cs           = (const float*)d_in[18];
    const float* W_edge         = (const float*)d_in[19];
    const float* b_edge         = (const float*)d_in[20];
    const float* W_ef           = (const float*)d_in[21];
    const float* b_ef           = (const float*)d_in[22];
    float* out = (float*)d_out;

    cudaFuncSetAttribute(node_kernel, cudaFuncAttributeMaxDynamicSharedMemorySize, SMEM_NODE);
    cudaFuncSetAttribute(edge1_hmma,  cudaFuncAttributeMaxDynamicSharedMemorySize, SMEM_E1);
    cudaFuncSetAttribute(edge2_hmma,  cudaFuncAttributeMaxDynamicSharedMemorySize, SMEM_E2);

    int nsm = 148;
    cudaDeviceGetAttribute(&nsm, cudaDevAttrMultiProcessorCount, 0);

    cs_kernel<<<NG, 256>>>(charge, spin, emb_chg, emb_spin, W_cs, b_cs);
    node_kernel<<<nsm, 256, SMEM_NODE>>>(atomic_numbers, nde, nbatch, emb_atom,
                                         W_nd, b_nd, ln_g, ln_b, W_node, b_node);
    edge1_hmma<<<nsm, 512, SMEM_E1>>>(edist, edir, W_edge, b_edge);
    edge2_hmma<<<nsm, 512, SMEM_E2>>>(nsrc, W_ef, b_ef, out);
}